// round 6
// baseline (speedup 1.0000x reference)
#include <cuda_runtime.h>
#include <cstdint>

#define B_  4
#define H_  8
#define BH_ 32
#define L_  8192
#define D_  64
#define C_  256
#define W_  32

// ---------------- scratch (device globals; no cudaMalloc allowed) ----------
__device__ float  g_dists[(size_t)BH_ * C_ * L_];   // 256 MB, layout [bh][c][l]
__device__ float  g_sums[H_ * C_ * D_];
__device__ int    g_bins[H_ * C_];
__device__ float  g_msq[H_ * C_];
__device__ double g_loss;

#define NEG_INF __int_as_float(0xff800000)

// =========================== init: zero + means row norms ==================
__global__ void init_kernel(const float* __restrict__ means) {
    int row = blockIdx.x;          // h*C + c  (2048 rows)
    int t   = threadIdx.x;         // 64
    float m = means[row * D_ + t];
    g_sums[row * D_ + t] = 0.0f;
    float v = m * m;
    #pragma unroll
    for (int o = 16; o > 0; o >>= 1) v += __shfl_down_sync(0xffffffffu, v, o);
    __shared__ float sh[2];
    if ((t & 31) == 0) sh[t >> 5] = v;
    __syncthreads();
    if (t == 0) {
        g_msq[row]  = sh[0] + sh[1];
        g_bins[row] = 0;
        if (row == 0) g_loss = 0.0;
    }
}

// =========================== fused GEMM + argmax + scatter + loss ==========
// Block: 64 tokens x 256 clusters of one (b,h). 256 threads.
// tc = tid & 15 -> clusters {g*64 + tc*4 + i : g=0..3, i=0..3}
// tr = tid >> 4 -> tokens tr*4 .. tr*4+3
#define MS_STRIDE 260
#define XS_STRIDE 65
#define SMEM_FLOATS (64*MS_STRIDE + 64*XS_STRIDE + 1024 + 1024 + 64 + 64)
#define SMEM_BYTES  (SMEM_FLOATS * 4)

__global__ void __launch_bounds__(256, 2)
gemm_kernel(const float* __restrict__ x, const float* __restrict__ means) {
    extern __shared__ float smem[];
    float* Ms    = smem;                         // [64][260]  Ms[k][c]
    float* Xs    = Ms + 64 * MS_STRIDE;          // [64][65]   Xs[t][k]
    float* sv    = Xs + 64 * XS_STRIDE;          // [64][16]
    int*   si    = (int*)(sv + 1024);            // [64][16]
    int*   sb    = si + 1024;                    // [64] bucket per token
    float* sloss = (float*)(sb + 64);            // [64]

    const int tid = threadIdx.x;
    const int bh  = blockIdx.y;
    const int h   = bh & 7;
    const int l0  = blockIdx.x * 64;
    const float* xp = x + ((size_t)bh * L_ + l0) * D_;
    const float* mp = means + (size_t)h * C_ * D_;

    // load means slice transposed: Ms[d][c] = mp[c*64+d]  (coalesced global)
    #pragma unroll 4
    for (int i = 0; i < 64; i++) {
        int idx = tid + i * 256;
        Ms[(idx & 63) * MS_STRIDE + (idx >> 6)] = mp[idx];
    }
    // load X tile natural: Xs[t][d]
    #pragma unroll 4
    for (int i = 0; i < 16; i++) {
        int idx = tid + i * 256;
        Xs[(idx >> 6) * XS_STRIDE + (idx & 63)] = xp[idx];
    }
    __syncthreads();

    const int tc = tid & 15;
    const int tr = tid >> 4;

    unsigned long long acc[4][8];   // [token][cluster-pair], f32x2
    #pragma unroll
    for (int j = 0; j < 4; j++)
        #pragma unroll
        for (int p = 0; p < 8; p++) acc[j][p] = 0ULL;

    #pragma unroll 4
    for (int k = 0; k < 64; k++) {
        float a0 = Xs[(tr * 4 + 0) * XS_STRIDE + k];
        float a1 = Xs[(tr * 4 + 1) * XS_STRIDE + k];
        float a2 = Xs[(tr * 4 + 2) * XS_STRIDE + k];
        float a3 = Xs[(tr * 4 + 3) * XS_STRIDE + k];
        unsigned long long ap[4];
        asm("mov.b64 %0, {%1, %1};" : "=l"(ap[0]) : "f"(a0));
        asm("mov.b64 %0, {%1, %1};" : "=l"(ap[1]) : "f"(a1));
        asm("mov.b64 %0, {%1, %1};" : "=l"(ap[2]) : "f"(a2));
        asm("mov.b64 %0, {%1, %1};" : "=l"(ap[3]) : "f"(a3));
        unsigned long long bp[8];
        #pragma unroll
        for (int g = 0; g < 4; g++) {
            ulonglong2 bb = *(const ulonglong2*)(Ms + k * MS_STRIDE + g * 64 + tc * 4);
            bp[g * 2 + 0] = bb.x;
            bp[g * 2 + 1] = bb.y;
        }
        #pragma unroll
        for (int j = 0; j < 4; j++)
            #pragma unroll
            for (int p = 0; p < 8; p++)
                asm("fma.rn.f32x2 %0, %1, %2, %0;"
                    : "+l"(acc[j][p]) : "l"(ap[j]), "l"(bp[p]));
    }

    // --------- store dists transposed [bh][c][l], float4 along l ----------
    float* dp = g_dists + (size_t)bh * C_ * L_ + l0;
    #pragma unroll
    for (int g = 0; g < 4; g++)
        #pragma unroll
        for (int i = 0; i < 4; i++) {
            int c = g * 64 + tc * 4 + i;
            int p = g * 2 + (i >> 1);
            float4 st;
            if (i & 1) {
                st.x = __uint_as_float((unsigned)(acc[0][p] >> 32));
                st.y = __uint_as_float((unsigned)(acc[1][p] >> 32));
                st.z = __uint_as_float((unsigned)(acc[2][p] >> 32));
                st.w = __uint_as_float((unsigned)(acc[3][p] >> 32));
            } else {
                st.x = __uint_as_float((unsigned)acc[0][p]);
                st.y = __uint_as_float((unsigned)acc[1][p]);
                st.z = __uint_as_float((unsigned)acc[2][p]);
                st.w = __uint_as_float((unsigned)acc[3][p]);
            }
            *(float4*)(dp + (size_t)c * L_ + tr * 4) = st;
        }

    // --------- local argmax over this thread's 16 clusters (c ascending) --
    float bv[4] = {NEG_INF, NEG_INF, NEG_INF, NEG_INF};
    int   bi[4] = {0, 0, 0, 0};
    #pragma unroll
    for (int g = 0; g < 4; g++)
        #pragma unroll
        for (int i = 0; i < 4; i++) {
            int c = g * 64 + tc * 4 + i;
            int p = g * 2 + (i >> 1);
            #pragma unroll
            for (int j = 0; j < 4; j++) {
                unsigned u = (i & 1) ? (unsigned)(acc[j][p] >> 32) : (unsigned)acc[j][p];
                float v = __uint_as_float(u);
                if (v > bv[j]) { bv[j] = v; bi[j] = c; }
            }
        }
    #pragma unroll
    for (int j = 0; j < 4; j++) {
        sv[(tr * 4 + j) * 16 + tc] = bv[j];
        si[(tr * 4 + j) * 16 + tc] = bi[j];
    }
    __syncthreads();

    // --------- per-token reduce, loss term, bins ---------------------------
    if (tid < 64) {
        int t = tid;
        float best = sv[t * 16];
        int   idx  = si[t * 16];
        #pragma unroll
        for (int u = 1; u < 16; u++) {
            float v = sv[t * 16 + u];
            int   d = si[t * 16 + u];
            if (v > best || (v == best && d < idx)) { best = v; idx = d; }
        }
        sb[t] = idx;
        float xsq = 0.0f;
        #pragma unroll
        for (int k = 0; k < 64; k++) {
            float xv = Xs[t * XS_STRIDE + k];
            xsq = fmaf(xv, xv, xsq);
        }
        sloss[t] = xsq - 2.0f * best + g_msq[h * C_ + idx];
        atomicAdd(&g_bins[h * C_ + idx], 1);
    }
    __syncthreads();

    if (tid == 0) {
        float s = 0.0f;
        #pragma unroll 8
        for (int i = 0; i < 64; i++) s += sloss[i];
        atomicAdd(&g_loss, (double)s);
    }

    // --------- scatter x into cluster sums (vector red) --------------------
    {
        int t = tid >> 2;
        int q = tid & 3;
        int bucket = sb[t];
        float* dst = g_sums + ((size_t)(h * C_ + bucket)) * D_ + q * 16;
        const float* src = Xs + t * XS_STRIDE + q * 16;
        #pragma unroll
        for (int m = 0; m < 4; m++) {
            float v0 = src[m * 4 + 0], v1 = src[m * 4 + 1];
            float v2 = src[m * 4 + 2], v3 = src[m * 4 + 3];
            asm volatile("red.global.add.v4.f32 [%0], {%1,%2,%3,%4};"
                         :: "l"(dst + m * 4), "f"(v0), "f"(v1), "f"(v2), "f"(v3)
                         : "memory");
        }
    }
}

// =========================== top-32 per (bh, c) column ======================
__global__ void __launch_bounds__(256) topk_kernel(float* __restrict__ out) {
    const int col = blockIdx.x;                 // bh*C + c, 8192 columns
    const float* p = g_dists + (size_t)col * L_;
    const int tid = threadIdx.x;

    float v[32];
    #pragma unroll
    for (int ch = 0; ch < 8; ch++) {
        float4 q = *(const float4*)(p + ch * 1024 + tid * 4);
        v[ch * 4 + 0] = q.x; v[ch * 4 + 1] = q.y;
        v[ch * 4 + 2] = q.z; v[ch * 4 + 3] = q.w;
    }
    // local best (lowest index wins ties; scan in ascending l order)
    float lv = NEG_INF; int li = 0;
    #pragma unroll
    for (int e = 0; e < 32; e++) {
        int l = (e >> 2) * 1024 + tid * 4 + (e & 3);
        if (v[e] > lv) { lv = v[e]; li = l; }
    }

    __shared__ float wv[8];
    __shared__ int   wi[8];
    __shared__ int   winners[32];
    __shared__ int   fwi;

    for (int r = 0; r < W_; r++) {
        float mv = lv; int mi = li;
        #pragma unroll
        for (int o = 16; o > 0; o >>= 1) {
            float ov = __shfl_down_sync(0xffffffffu, mv, o);
            int   oi = __shfl_down_sync(0xffffffffu, mi, o);
            if (ov > mv || (ov == mv && oi < mi)) { mv = ov; mi = oi; }
        }
        if ((tid & 31) == 0) { wv[tid >> 5] = mv; wi[tid >> 5] = mi; }
        __syncthreads();
        if (tid == 0) {
            float bvv = wv[0]; int bii = wi[0];
            #pragma unroll
            for (int u = 1; u < 8; u++)
                if (wv[u] > bvv || (wv[u] == bvv && wi[u] < bii)) { bvv = wv[u]; bii = wi[u]; }
            winners[r] = bii;
            fwi = bii;
        }
        __syncthreads();
        int Wi = fwi;
        if (li == Wi) {             // exactly one owner; it rescans
            #pragma unroll
            for (int e = 0; e < 32; e++) {
                int l = (e >> 2) * 1024 + tid * 4 + (e & 3);
                if (l == Wi) v[e] = NEG_INF;
            }
            lv = NEG_INF; li = 0;
            #pragma unroll
            for (int e = 0; e < 32; e++) {
                int l = (e >> 2) * 1024 + tid * 4 + (e & 3);
                if (v[e] > lv) { lv = v[e]; li = l; }
            }
        }
    }

    // bitonic sort of 32 winner indices ascending (warp 0)
    if (tid < 32) {
        int key = winners[tid];
        #pragma unroll
        for (int k = 2; k <= 32; k <<= 1)
            #pragma unroll
            for (int j = k >> 1; j > 0; j >>= 1) {
                int other = __shfl_xor_sync(0xffffffffu, key, j);
                bool up    = (tid & k) == 0;
                bool lower = (tid & j) == 0;
                int mn = min(key, other), mx = max(key, other);
                key = (up == lower) ? mn : mx;
            }
        out[(size_t)col * W_ + tid] = (float)key;
    }
}

// =========================== finalize: new_means + loss ====================
#define IDX_COUNT (BH_ * C_ * W_)        // 262144
__global__ void finalize_kernel(const float* __restrict__ means,
                                float* __restrict__ out) {
    int row = blockIdx.x;                // h*C + c
    int t   = threadIdx.x;               // 64
    float s = g_sums[row * D_ + t];
    float v = s * s;
    #pragma unroll
    for (int o = 16; o > 0; o >>= 1) v += __shfl_down_sync(0xffffffffu, v, o);
    __shared__ float sh[2];
    if ((t & 31) == 0) sh[t >> 5] = v;
    __syncthreads();
    float norm  = sqrtf(sh[0] + sh[1]);
    float denom = fmaxf(norm, 1e-12f);
    float val   = (g_bins[row] == 0) ? means[row * D_ + t] : s / denom;
    out[IDX_COUNT + 1 + row * D_ + t] = val;
    if (row == 0 && t == 0)
        out[IDX_COUNT] = (float)(g_loss * (1e-4 / 16777216.0));
}

// =========================== launcher ======================================
extern "C" void kernel_launch(void* const* d_in, const int* in_sizes, int n_in,
                              void* d_out, int out_size) {
    const float* x     = (const float*)d_in[0];
    const float* means = (const float*)d_in[1];
    float* out = (float*)d_out;

    cudaFuncSetAttribute(gemm_kernel,
                         cudaFuncAttributeMaxDynamicSharedMemorySize, SMEM_BYTES);

    init_kernel<<<H_ * C_, 64>>>(means);
    dim3 grid(L_ / 64, BH_);
    gemm_kernel<<<grid, 256, SMEM_BYTES>>>(x, means);
    topk_kernel<<<BH_ * C_, 256>>>(out);
    finalize_kernel<<<H_ * C_, 64>>>(means, out);
}